// round 10
// baseline (speedup 1.0000x reference)
#include <cuda_runtime.h>
#include <cuda_bf16.h>
#include <cstdint>

// ===================== helpers =====================

__device__ __forceinline__ uint32_t smem_u32(const void* p) {
    uint32_t a;
    asm("{ .reg .u64 t; cvta.to.shared.u64 t, %1; cvt.u32.u64 %0, t; }" : "=r"(a) : "l"(p));
    return a;
}

#define LDMATRIX_X4(r0, r1, r2, r3, addr) \
    asm volatile("ldmatrix.sync.aligned.m8n8.x4.shared.b16 {%0,%1,%2,%3}, [%4];" \
        : "=r"(r0), "=r"(r1), "=r"(r2), "=r"(r3) : "r"(addr))

#define MMA16816(c, a0, a1, a2, a3, b0, b1) \
    asm volatile("mma.sync.aligned.m16n8k16.row.col.f32.bf16.bf16.f32 " \
        "{%0,%1,%2,%3}, {%4,%5,%6,%7}, {%8,%9}, {%0,%1,%2,%3};" \
        : "+f"((c)[0]), "+f"((c)[1]), "+f"((c)[2]), "+f"((c)[3]) \
        : "r"(a0), "r"(a1), "r"(a2), "r"(a3), "r"(b0), "r"(b1))

// ===================== Problem constants =====================

#define NN      16384
#define NFEAT   256
#define NHID    64
#define KC      64            // K chunk per pipeline step
#define NCHUNK  (NN / KC)     // 256
#define KSPLIT  2
#define NCH_H   (NCHUNK / KSPLIT)  // 128 chunks per CTA
#define MTILE   128
#define NMT     (NN / MTILE)  // 128 M-tiles
#define K3_GRID 1024          // x 4 warps = 4096 row-groups of 4 rows

// Scratch (static device globals — allocation-free)
__device__ __align__(16) unsigned char g_Bh[NCHUNK * 8192];   // pre-swizzled bf16 hi tiles [chunk][64n x 64k]
__device__ __align__(16) unsigned char g_Bl[NCHUNK * 8192];   // bf16 lo tiles
__device__ __align__(16) float g_BT[16 * NN];                 // fp32 B^T, cols 48..63 only: [j][k]
__device__ __align__(16) float g_Hpart[KSPLIT * NN * NHID];   // partial pre-activation sums (8MB)
__device__ __align__(16) float g_G[NN * 2];                   // h1 @ W2 (before +b2)
__device__ __align__(16) float g_pmax[K3_GRID * 4 * 2];       // per-warp column maxes

// ===================== K1: B = x @ W1, split to bf16 hi/lo, pre-swizzled; B^T fp32 cols 48..63 =====================

__global__ __launch_bounds__(256) void k1_xw1(const float* __restrict__ x, const float* __restrict__ W1) {
    extern __shared__ char sm1[];
    float* W1s = (float*)sm1;                        // 65536 B
    unsigned char* bh = (unsigned char*)sm1 + 65536; // 8192 B
    unsigned char* bl = bh + 8192;

    int tid = threadIdx.x, wid = tid >> 5, lid = tid & 31;

    const float4* w4 = (const float4*)W1;
    float4* w4s = (float4*)W1s;
#pragma unroll
    for (int i = 0; i < 16; i++) w4s[tid + i * 256] = w4[tid + i * 256];
    __syncthreads();

    int b = blockIdx.x;   // chunk index; covers global k rows [64b, 64b+64)
    for (int i = 0; i < 8; i++) {
        int kl = wid * 8 + i;                 // local k row 0..63
        long k = (long)b * 64 + kl;
        const float* xr = x + k * 256;
        float a0 = 0.f, a1 = 0.f;             // n = 2*lid, 2*lid+1
#pragma unroll 8
        for (int j = 0; j < 256; j++) {
            float xv = __ldg(xr + j);
            float2 wv = *(const float2*)(W1s + j * 64 + 2 * lid);
            a0 = fmaf(xv, wv.x, a0);
            a1 = fmaf(xv, wv.y, a1);
        }
#pragma unroll
        for (int t = 0; t < 2; t++) {
            float a = t ? a1 : a0;
            int n = 2 * lid + t;
            unsigned off = n * 128 + kl * 2;
            unsigned sw = off ^ ((off >> 3) & 0x70);
            __nv_bfloat16 h = __float2bfloat16(a);
            __nv_bfloat16 l = __float2bfloat16(a - __bfloat162float(h));
            *(__nv_bfloat16*)(bh + sw) = h;
            *(__nv_bfloat16*)(bl + sw) = l;
            if (n >= 48) g_BT[(size_t)(n - 48) * NN + k] = a;   // fp32 B^T for FFMA cols
        }
    }
    __syncthreads();

    int4* gh = (int4*)g_Bh + (size_t)b * 512;
    int4* gl = (int4*)g_Bl + (size_t)b * 512;
    const int4* sh = (const int4*)bh;
    const int4* sl = (const int4*)bl;
#pragma unroll
    for (int i = 0; i < 2; i++) {
        gh[tid + i * 256] = sh[tid + i * 256];
        gl[tid + i * 256] = sl[tid + i * 256];
    }
}

// ===================== K2: pass 1 partial — hybrid tensor (cols 0..47) + fp32 FFMA (cols 48..63) =====================
// grid 256 (= 128 M-tiles x 2 K-halves), block 256, 2 CTAs/SM.
// Tensor: bf16 hi/lo Markidis 3-term on n-tiles 0..5 (72 MMA/warp/chunk).
// FFMA:   exact fp32 for n 48..63 into acc[6],acc[7], riding the idle fma pipe.

__global__ __launch_bounds__(256, 2) void k2_pass1(const float* __restrict__ adj) {
    extern __shared__ char sm2raw[];
    uint32_t raw = smem_u32(sm2raw);
    uint32_t pad = (1024u - (raw & 1023u)) & 1023u;
    char* sm = sm2raw + pad;
    uint32_t smb = raw + pad;

    const int BUFSZ = 49152;

    int tid = threadIdx.x, wid = tid >> 5, lane = tid & 31;

    int mt   = blockIdx.x >> 1;        // M-tile 0..127
    int half = blockIdx.x & 1;         // K half
    int rb = mt * MTILE;
    int c0 = half * NCH_H;

    float acc[8][4];
#pragma unroll
    for (int i = 0; i < 8; i++)
#pragma unroll
        for (int j = 0; j < 4; j++) acc[i][j] = 0.f;

    int rloc = lane & 15;
    uint32_t aRow = (uint32_t)((wid * 16 + rloc) * 128);
    uint32_t aHi  = (uint32_t)(lane >> 4);
    uint32_t aRx  = (uint32_t)(rloc & 7);
    int nloc = (lane & 7) + ((lane >> 4) << 3);
    uint32_t bKh = (uint32_t)((lane >> 3) & 1);
    uint32_t bNx = (uint32_t)(lane & 7);
    uint32_t bRow = (uint32_t)(nloc * 128);

    // FFMA lane geometry: rows r0, r0+8; cols 48+cb,49+cb,56+cb,57+cb (cb = 2*(lane&3))
    int ffr0 = rb + wid * 16 + (lane >> 2);
    int ffcb = 2 * (lane & 3);
    const float* bt0 = g_BT + (size_t)(ffcb)     * NN;
    const float* bt1 = g_BT + (size_t)(ffcb + 1) * NN;
    const float* bt2 = g_BT + (size_t)(ffcb + 8) * NN;
    const float* bt3 = g_BT + (size_t)(ffcb + 9) * NN;

    float4 v[8];
    int4 bh0, bh1, bl0, bl1;

    auto issue_loads = [&](int ci) {
#pragma unroll
        for (int q = 0; q < 8; q++) {
            int li = q * 256 + tid;
            int row = li >> 4, qk = li & 15;
            v[q] = __ldg((const float4*)(adj + (long)(rb + row) * NN + (long)ci * KC) + qk);
        }
        const int4* gbh = (const int4*)g_Bh + (size_t)ci * 512;
        const int4* gbl = (const int4*)g_Bl + (size_t)ci * 512;
        bh0 = __ldg(gbh + tid); bh1 = __ldg(gbh + tid + 256);
        bl0 = __ldg(gbl + tid); bl1 = __ldg(gbl + tid + 256);
    };

    auto store_chunk = [&](char* buf) {
#pragma unroll
        for (int q = 0; q < 8; q++) {
            int li = q * 256 + tid;
            int row = li >> 4, qk = li & 15;
            unsigned off = row * 128 + qk * 8;
            unsigned sw = off ^ ((row & 7) << 4);
            uint32_t h01, h23, l01, l23;
            asm("cvt.rn.bf16x2.f32 %0, %1, %2;" : "=r"(h01) : "f"(v[q].y), "f"(v[q].x));
            asm("cvt.rn.bf16x2.f32 %0, %1, %2;" : "=r"(h23) : "f"(v[q].w), "f"(v[q].z));
            float lx = v[q].x - __uint_as_float(h01 << 16);
            float ly = v[q].y - __uint_as_float(h01 & 0xffff0000u);
            float lz = v[q].z - __uint_as_float(h23 << 16);
            float lw = v[q].w - __uint_as_float(h23 & 0xffff0000u);
            asm("cvt.rn.bf16x2.f32 %0, %1, %2;" : "=r"(l01) : "f"(ly), "f"(lx));
            asm("cvt.rn.bf16x2.f32 %0, %1, %2;" : "=r"(l23) : "f"(lw), "f"(lz));
            *(uint2*)(buf + 0     + sw) = make_uint2(h01, h23);
            *(uint2*)(buf + 16384 + sw) = make_uint2(l01, l23);
        }
        ((int4*)(buf + 32768))[tid] = bh0; ((int4*)(buf + 32768))[tid + 256] = bh1;
        ((int4*)(buf + 40960))[tid] = bl0; ((int4*)(buf + 40960))[tid + 256] = bl1;
    };

    // tensor MMAs on n-tiles 0..5 only
    auto compute = [&](uint32_t bufaddr) {
        uint32_t AH_ = bufaddr, AL_ = bufaddr + 16384;
        uint32_t BH_ = bufaddr + 32768, BL_ = bufaddr + 40960;
#pragma unroll
        for (int ks = 0; ks < 4; ks++) {
            uint32_t au = ((((uint32_t)(ks * 2)) + aHi) ^ aRx) << 4;
            uint32_t ah[4], al[4];
            LDMATRIX_X4(ah[0], ah[1], ah[2], ah[3], AH_ + aRow + au);
            LDMATRIX_X4(al[0], al[1], al[2], al[3], AL_ + aRow + au);
            uint32_t bu = ((((uint32_t)(ks * 2)) + bKh) ^ bNx) << 4;
#pragma unroll
            for (int ntp = 0; ntp < 3; ntp++) {
                uint32_t bh[4], bl[4];
                LDMATRIX_X4(bh[0], bh[1], bh[2], bh[3], BH_ + bRow + bu + ntp * 2048);
                LDMATRIX_X4(bl[0], bl[1], bl[2], bl[3], BL_ + bRow + bu + ntp * 2048);
                MMA16816(acc[2 * ntp],     ah[0], ah[1], ah[2], ah[3], bh[0], bh[1]);
                MMA16816(acc[2 * ntp],     al[0], al[1], al[2], al[3], bh[0], bh[1]);
                MMA16816(acc[2 * ntp],     ah[0], ah[1], ah[2], ah[3], bl[0], bl[1]);
                MMA16816(acc[2 * ntp + 1], ah[0], ah[1], ah[2], ah[3], bh[2], bh[3]);
                MMA16816(acc[2 * ntp + 1], al[0], al[1], al[2], al[3], bh[2], bh[3]);
                MMA16816(acc[2 * ntp + 1], ah[0], ah[1], ah[2], ah[3], bl[2], bl[3]);
            }
        }
    };

    // exact fp32 FFMA for cols 48..63 of this chunk (reads adj/B^T via L2)
    auto compute_ffma = [&](int ci) {
        const float4* a0r = (const float4*)(adj + (size_t)ffr0 * NN + (size_t)ci * KC);
        const float4* a1r = (const float4*)(adj + (size_t)(ffr0 + 8) * NN + (size_t)ci * KC);
        const float4* B0 = (const float4*)(bt0 + (size_t)ci * KC);
        const float4* B1 = (const float4*)(bt1 + (size_t)ci * KC);
        const float4* B2 = (const float4*)(bt2 + (size_t)ci * KC);
        const float4* B3 = (const float4*)(bt3 + (size_t)ci * KC);
#pragma unroll 4
        for (int kb = 0; kb < 16; kb++) {
            float4 A0 = __ldg(a0r + kb);
            float4 A1 = __ldg(a1r + kb);
            float4 b0 = __ldg(B0 + kb);
            float4 b1 = __ldg(B1 + kb);
            float4 b2 = __ldg(B2 + kb);
            float4 b3 = __ldg(B3 + kb);
            acc[6][0] = fmaf(A0.x, b0.x, acc[6][0]); acc[6][1] = fmaf(A0.x, b1.x, acc[6][1]);
            acc[6][2] = fmaf(A1.x, b0.x, acc[6][2]); acc[6][3] = fmaf(A1.x, b1.x, acc[6][3]);
            acc[7][0] = fmaf(A0.x, b2.x, acc[7][0]); acc[7][1] = fmaf(A0.x, b3.x, acc[7][1]);
            acc[7][2] = fmaf(A1.x, b2.x, acc[7][2]); acc[7][3] = fmaf(A1.x, b3.x, acc[7][3]);
            acc[6][0] = fmaf(A0.y, b0.y, acc[6][0]); acc[6][1] = fmaf(A0.y, b1.y, acc[6][1]);
            acc[6][2] = fmaf(A1.y, b0.y, acc[6][2]); acc[6][3] = fmaf(A1.y, b1.y, acc[6][3]);
            acc[7][0] = fmaf(A0.y, b2.y, acc[7][0]); acc[7][1] = fmaf(A0.y, b3.y, acc[7][1]);
            acc[7][2] = fmaf(A1.y, b2.y, acc[7][2]); acc[7][3] = fmaf(A1.y, b3.y, acc[7][3]);
            acc[6][0] = fmaf(A0.z, b0.z, acc[6][0]); acc[6][1] = fmaf(A0.z, b1.z, acc[6][1]);
            acc[6][2] = fmaf(A1.z, b0.z, acc[6][2]); acc[6][3] = fmaf(A1.z, b1.z, acc[6][3]);
            acc[7][0] = fmaf(A0.z, b2.z, acc[7][0]); acc[7][1] = fmaf(A0.z, b3.z, acc[7][1]);
            acc[7][2] = fmaf(A1.z, b2.z, acc[7][2]); acc[7][3] = fmaf(A1.z, b3.z, acc[7][3]);
            acc[6][0] = fmaf(A0.w, b0.w, acc[6][0]); acc[6][1] = fmaf(A0.w, b1.w, acc[6][1]);
            acc[6][2] = fmaf(A1.w, b0.w, acc[6][2]); acc[6][3] = fmaf(A1.w, b1.w, acc[6][3]);
            acc[7][0] = fmaf(A0.w, b2.w, acc[7][0]); acc[7][1] = fmaf(A0.w, b3.w, acc[7][1]);
            acc[7][2] = fmaf(A1.w, b2.w, acc[7][2]); acc[7][3] = fmaf(A1.w, b3.w, acc[7][3]);
        }
    };

    issue_loads(c0);
    store_chunk(sm);
    __syncthreads();

    for (int it = 0; it < NCH_H - 1; it++) {
        int s = it & 1;
        issue_loads(c0 + it + 1);
        compute(smb + s * BUFSZ);          // 72 MMAs issued (async on tensor pipe)
        store_chunk(sm + (s ^ 1) * BUFSZ); // frees v[] regs
        compute_ffma(c0 + it);             // fp32 cols while tensor pipe drains
        __syncthreads();
    }
    compute(smb + ((NCH_H - 1) & 1) * BUFSZ);
    compute_ffma(c0 + NCH_H - 1);

    float* hp = g_Hpart + (size_t)half * NN * NHID;
    int r0 = rb + wid * 16 + (lane >> 2);
    int ncol = 2 * (lane & 3);
#pragma unroll
    for (int nt = 0; nt < 8; nt++) {
        *(float2*)(hp + (size_t)r0 * NHID + nt * 8 + ncol)       = make_float2(acc[nt][0], acc[nt][1]);
        *(float2*)(hp + (size_t)(r0 + 8) * NHID + nt * 8 + ncol) = make_float2(acc[nt][2], acc[nt][3]);
    }
}

// ===================== K2b: combine halves, +b1, relu, @W2 -> g_G =====================

__global__ __launch_bounds__(256) void k2b_combine(const float* __restrict__ b1,
                                                   const float* __restrict__ W2) {
    __shared__ float sb1[64];
    __shared__ float sW2[128];
    int tid = threadIdx.x;
    if (tid < 64)  sb1[tid] = b1[tid];
    if (tid >= 128 && tid < 256) sW2[tid - 128] = W2[tid - 128];
    __syncthreads();

    int row = blockIdx.x * 256 + tid;
    const float4* p0 = (const float4*)(g_Hpart) + (size_t)row * 16;
    const float4* p1 = (const float4*)(g_Hpart + (size_t)NN * NHID) + (size_t)row * 16;
    float g0 = 0.f, g1 = 0.f;
#pragma unroll
    for (int i = 0; i < 16; i++) {
        float4 a = __ldg(p0 + i);
        float4 b = __ldg(p1 + i);
        int n = i * 4;
        float h;
        h = fmaxf(a.x + b.x + sb1[n + 0], 0.f); g0 = fmaf(h, sW2[2*n + 0], g0); g1 = fmaf(h, sW2[2*n + 1], g1);
        h = fmaxf(a.y + b.y + sb1[n + 1], 0.f); g0 = fmaf(h, sW2[2*n + 2], g0); g1 = fmaf(h, sW2[2*n + 3], g1);
        h = fmaxf(a.z + b.z + sb1[n + 2], 0.f); g0 = fmaf(h, sW2[2*n + 4], g0); g1 = fmaf(h, sW2[2*n + 5], g1);
        h = fmaxf(a.w + b.w + sb1[n + 3], 0.f); g0 = fmaf(h, sW2[2*n + 6], g0); g1 = fmaf(h, sW2[2*n + 7], g1);
    }
    ((float2*)g_G)[row] = make_float2(g0, g1);
}

// ===================== K3: pass 2 — H2 = adj @ G, per-warp max =====================
// grid 1024, block 128. Each warp: 4 rows (r, r+4096, r+8192, r+12288) sharing G loads.
// A-prefetch only (G is L1/L2 resident); adj streamed evict-first. ~58 regs -> higher occ.

__global__ __launch_bounds__(128) void k3_pass2(const float* __restrict__ adj) {
    int tid = threadIdx.x, wid = tid >> 5, lane = tid & 31;
    int grp = blockIdx.x * 4 + wid;               // 0..4095

    const float4* a0p = (const float4*)(adj + (size_t)grp * NN);
    const float4* a1p = (const float4*)(adj + (size_t)(grp + 4096) * NN);
    const float4* a2p = (const float4*)(adj + (size_t)(grp + 8192) * NN);
    const float4* a3p = (const float4*)(adj + (size_t)(grp + 12288) * NN);
    const float4* g4 = (const float4*)g_G;

    float s00 = 0.f, s01 = 0.f, s10 = 0.f, s11 = 0.f;
    float s20 = 0.f, s21 = 0.f, s30 = 0.f, s31 = 0.f;

    float4 A0 = __ldcs(a0p + lane);
    float4 A1 = __ldcs(a1p + lane);
    float4 A2 = __ldcs(a2p + lane);
    float4 A3 = __ldcs(a3p + lane);

#define K3_FMA(G0, G1) do { \
        s00 = fmaf(A0.x, G0.x, s00); s01 = fmaf(A0.x, G0.y, s01); \
        s10 = fmaf(A1.x, G0.x, s10); s11 = fmaf(A1.x, G0.y, s11); \
        s20 = fmaf(A2.x, G0.x, s20); s21 = fmaf(A2.x, G0.y, s21); \
        s30 = fmaf(A3.x, G0.x, s30); s31 = fmaf(A3.x, G0.y, s31); \
        s00 = fmaf(A0.y, G0.z, s00); s01 = fmaf(A0.y, G0.w, s01); \
        s10 = fmaf(A1.y, G0.z, s10); s11 = fmaf(A1.y, G0.w, s11); \
        s20 = fmaf(A2.y, G0.z, s20); s21 = fmaf(A2.y, G0.w, s21); \
        s30 = fmaf(A3.y, G0.z, s30); s31 = fmaf(A3.y, G0.w, s31); \
        s00 = fmaf(A0.z, G1.x, s00); s01 = fmaf(A0.z, G1.y, s01); \
        s10 = fmaf(A1.z, G1.x, s10); s11 = fmaf(A1.z, G1.y, s11); \
        s20 = fmaf(A2.z, G1.x, s20); s21 = fmaf(A2.z, G1.y, s21); \
        s30 = fmaf(A3.z, G1.x, s30); s31 = fmaf(A3.z, G1.y, s31); \
        s00 = fmaf(A0.w, G1.z, s00); s01 = fmaf(A0.w, G1.w, s01); \
        s10 = fmaf(A1.w, G1.z, s10); s11 = fmaf(A1.w, G1.w, s11); \
        s20 = fmaf(A2.w, G1.z, s20); s21 = fmaf(A2.w, G1.w, s21); \
        s30 = fmaf(A3.w, G1.z, s30); s31 = fmaf(A3.w, G1.w, s31); \
    } while (0)

    for (int it = 1; it < 128; it++) {
        int jc = (it - 1) * 32 + lane;       // current consumption index
        int jn = it * 32 + lane;
        float4 nA0 = __ldcs(a0p + jn);
        float4 nA1 = __ldcs(a1p + jn);
        float4 nA2 = __ldcs(a2p + jn);
        float4 nA3 = __ldcs(a3p + jn);
        float4 G0 = __ldg(g4 + 2 * jc);
        float4 G1 = __ldg(g4 + 2 * jc + 1);
        K3_FMA(G0, G1);
        A0 = nA0; A1 = nA1; A2 = nA2; A3 = nA3;
    }
    {
        int jc = 127 * 32 + lane;
        float4 G0 = __ldg(g4 + 2 * jc);
        float4 G1 = __ldg(g4 + 2 * jc + 1);
        K3_FMA(G0, G1);
    }
#undef K3_FMA

#pragma unroll
    for (int o = 16; o; o >>= 1) {
        s00 += __shfl_xor_sync(0xFFFFFFFFu, s00, o);
        s01 += __shfl_xor_sync(0xFFFFFFFFu, s01, o);
        s10 += __shfl_xor_sync(0xFFFFFFFFu, s10, o);
        s11 += __shfl_xor_sync(0xFFFFFFFFu, s11, o);
        s20 += __shfl_xor_sync(0xFFFFFFFFu, s20, o);
        s21 += __shfl_xor_sync(0xFFFFFFFFu, s21, o);
        s30 += __shfl_xor_sync(0xFFFFFFFFu, s30, o);
        s31 += __shfl_xor_sync(0xFFFFFFFFu, s31, o);
    }
    if (lane == 0) {
        float m0 = fmaxf(fmaxf(s00, s10), fmaxf(s20, s30));
        float m1 = fmaxf(fmaxf(s01, s11), fmaxf(s21, s31));
        g_pmax[grp * 2]     = m0;
        g_pmax[grp * 2 + 1] = m1;
    }
}

// ===================== K4: final max reduce + Linear(2 -> 1) =====================

__global__ void k4_final(const float* __restrict__ W3, const float* __restrict__ b2,
                         const float* __restrict__ b3, float* __restrict__ out) {
    __shared__ float r[16];
    int tid = threadIdx.x;   // 256
    float m0 = -3.402823466e38f, m1 = -3.402823466e38f;
#pragma unroll
    for (int i = 0; i < (K3_GRID * 4) / 256; i++) {
        float2 p = ((const float2*)g_pmax)[i * 256 + tid];
        m0 = fmaxf(m0, p.x);
        m1 = fmaxf(m1, p.y);
    }
#pragma unroll
    for (int o = 16; o; o >>= 1) {
        m0 = fmaxf(m0, __shfl_xor_sync(0xFFFFFFFFu, m0, o));
        m1 = fmaxf(m1, __shfl_xor_sync(0xFFFFFFFFu, m1, o));
    }
    if ((tid & 31) == 0) { r[(tid >> 5) * 2] = m0; r[(tid >> 5) * 2 + 1] = m1; }
    __syncthreads();
    if (tid == 0) {
        float M0 = r[0], M1 = r[1];
#pragma unroll
        for (int w = 1; w < 8; w++) { M0 = fmaxf(M0, r[2 * w]); M1 = fmaxf(M1, r[2 * w + 1]); }
        M0 += b2[0];
        M1 += b2[1];
        out[0] = fmaf(M0, W3[0], fmaf(M1, W3[1], b3[0]));
    }
}

// ===================== Launch =====================

extern "C" void kernel_launch(void* const* d_in, const int* in_sizes, int n_in,
                              void* d_out, int out_size) {
    const float* x   = (const float*)d_in[0];
    const float* adj = (const float*)d_in[1];
    const float* W1  = (const float*)d_in[2];
    const float* b1  = (const float*)d_in[3];
    const float* W2  = (const float*)d_in[4];
    const float* b2  = (const float*)d_in[5];
    const float* W3  = (const float*)d_in[6];
    const float* b3  = (const float*)d_in[7];
    float* out = (float*)d_out;

    cudaFuncSetAttribute(k1_xw1,   cudaFuncAttributeMaxDynamicSharedMemorySize, 81920);
    cudaFuncSetAttribute(k2_pass1, cudaFuncAttributeMaxDynamicSharedMemorySize, 99328);

    k1_xw1<<<256, 256, 81920>>>(x, W1);
    k2_pass1<<<NMT * KSPLIT, 256, 99328>>>(adj);
    k2b_combine<<<64, 256>>>(b1, W2);
    k3_pass2<<<K3_GRID, 128>>>(adj);
    k4_final<<<1, 256>>>(W3, b2, b3, out);
}

// round 12
// speedup vs baseline: 1.3165x; 1.3165x over previous
#include <cuda_runtime.h>
#include <cuda_bf16.h>
#include <cstdint>

// ===================== helpers =====================

__device__ __forceinline__ uint32_t smem_u32(const void* p) {
    uint32_t a;
    asm("{ .reg .u64 t; cvta.to.shared.u64 t, %1; cvt.u32.u64 %0, t; }" : "=r"(a) : "l"(p));
    return a;
}

#define LDMATRIX_X4(r0, r1, r2, r3, addr) \
    asm volatile("ldmatrix.sync.aligned.m8n8.x4.shared.b16 {%0,%1,%2,%3}, [%4];" \
        : "=r"(r0), "=r"(r1), "=r"(r2), "=r"(r3) : "r"(addr))

#define MMA16816(c, a0, a1, a2, a3, b0, b1) \
    asm volatile("mma.sync.aligned.m16n8k16.row.col.f32.bf16.bf16.f32 " \
        "{%0,%1,%2,%3}, {%4,%5,%6,%7}, {%8,%9}, {%0,%1,%2,%3};" \
        : "+f"((c)[0]), "+f"((c)[1]), "+f"((c)[2]), "+f"((c)[3]) \
        : "r"(a0), "r"(a1), "r"(a2), "r"(a3), "r"(b0), "r"(b1))

// ===================== Problem constants =====================

#define NN      16384
#define NFEAT   256
#define NHID    64
#define KC      64            // K chunk per pipeline step
#define NCHUNK  (NN / KC)     // 256
#define KSPLIT  2
#define NCH_H   (NCHUNK / KSPLIT)  // 128 chunks per CTA
#define MTILE   128
#define NMT     (NN / MTILE)  // 128 M-tiles
#define K3_GRID 1024          // x 4 warps = 4096 row-groups of 4 rows

// k2 smem layout (per buffer)
#define AHo     0             // 16384: A bf16 hi, swizzled
#define ALo     16384         // 16384: A bf16 lo
#define BHo     32768         // 6144:  B bf16 hi, n-rows 0..47
#define BLo     38912         // 6144:  B bf16 lo
#define BFo     45056         // 4096:  B fp32 slice [k][16j] (cols 48..63)
#define ADJFo   49152         // 34816: adj fp32 [row][ADJ_STR]
#define ADJ_STR 68
#define BUFSZ   83968
#define SMEM_K2 (2 * BUFSZ + 1024)

// Scratch (static device globals — allocation-free)
__device__ __align__(16) unsigned char g_Bh[NCHUNK * 8192];   // pre-swizzled bf16 hi tiles [chunk][64n x 64k]
__device__ __align__(16) unsigned char g_Bl[NCHUNK * 8192];   // bf16 lo tiles
__device__ __align__(16) float g_BT2[NCHUNK * 1024];          // fp32 B slice [chunk][64k][16j] (cols 48..63)
__device__ __align__(16) float g_Hpart[KSPLIT * NN * NHID];   // partial pre-activation sums (8MB)
__device__ __align__(16) float g_G[NN * 2];                   // h1 @ W2 (before +b2)
__device__ __align__(16) float g_pmax[K3_GRID * 4 * 2];       // per-warp column maxes

// ===================== K1: B = x @ W1 -> bf16 hi/lo swizzled tiles + fp32 slice =====================

__global__ __launch_bounds__(256) void k1_xw1(const float* __restrict__ x, const float* __restrict__ W1) {
    extern __shared__ char sm1[];
    float* W1s = (float*)sm1;                        // 65536 B
    unsigned char* bh = (unsigned char*)sm1 + 65536; // 8192 B
    unsigned char* bl = bh + 8192;

    int tid = threadIdx.x, wid = tid >> 5, lid = tid & 31;

    const float4* w4 = (const float4*)W1;
    float4* w4s = (float4*)W1s;
#pragma unroll
    for (int i = 0; i < 16; i++) w4s[tid + i * 256] = w4[tid + i * 256];
    __syncthreads();

    int b = blockIdx.x;   // chunk index; covers global k rows [64b, 64b+64)
    for (int i = 0; i < 8; i++) {
        int kl = wid * 8 + i;                 // local k row 0..63
        long k = (long)b * 64 + kl;
        const float* xr = x + k * 256;
        float a0 = 0.f, a1 = 0.f;             // n = 2*lid, 2*lid+1
#pragma unroll 8
        for (int j = 0; j < 256; j++) {
            float xv = __ldg(xr + j);
            float2 wv = *(const float2*)(W1s + j * 64 + 2 * lid);
            a0 = fmaf(xv, wv.x, a0);
            a1 = fmaf(xv, wv.y, a1);
        }
#pragma unroll
        for (int t = 0; t < 2; t++) {
            float a = t ? a1 : a0;
            int n = 2 * lid + t;
            unsigned off = n * 128 + kl * 2;
            unsigned sw = off ^ ((off >> 3) & 0x70);
            __nv_bfloat16 h = __float2bfloat16(a);
            __nv_bfloat16 l = __float2bfloat16(a - __bfloat162float(h));
            *(__nv_bfloat16*)(bh + sw) = h;
            *(__nv_bfloat16*)(bl + sw) = l;
            if (n >= 48) g_BT2[(size_t)b * 1024 + kl * 16 + (n - 48)] = a;
        }
    }
    __syncthreads();

    int4* gh = (int4*)g_Bh + (size_t)b * 512;
    int4* gl = (int4*)g_Bl + (size_t)b * 512;
    const int4* sh = (const int4*)bh;
    const int4* sl = (const int4*)bl;
#pragma unroll
    for (int i = 0; i < 2; i++) {
        gh[tid + i * 256] = sh[tid + i * 256];
        gl[tid + i * 256] = sl[tid + i * 256];
    }
}

// ===================== K2: warp-specialized hybrid pass 1 =====================
// grid 256 (= 128 M-tiles x 2 K-halves), block 512, 1 CTA/SM.
// Warps 0-7: bf16 Markidis 3-term tensor path for cols 0..47 (72 MMA/warp/chunk).
// Warps 8-15: exact fp32 FFMA for cols 48..63 from SMEM (512 FMA + 192 LDS/warp/chunk).

__global__ __launch_bounds__(512, 1) void k2_pass1(const float* __restrict__ adj) {
    extern __shared__ char sm2raw[];
    uint32_t raw = smem_u32(sm2raw);
    uint32_t pad = (1024u - (raw & 1023u)) & 1023u;
    char* sm = sm2raw + pad;
    uint32_t smb = raw + pad;

    int tid = threadIdx.x, wid = tid >> 5, lane = tid & 31;

    int mt   = blockIdx.x >> 1;        // M-tile 0..127
    int half = blockIdx.x & 1;         // K half
    int rb = mt * MTILE;
    int c0 = half * NCH_H;

    // tensor-warp accumulators (cols 0..47)
    float acc[6][4];
#pragma unroll
    for (int i = 0; i < 6; i++)
#pragma unroll
        for (int j = 0; j < 4; j++) acc[i][j] = 0.f;

    // ffma-warp accumulators (cols 48..63)
    float facc[8];
#pragma unroll
    for (int i = 0; i < 8; i++) facc[i] = 0.f;

    // tensor ldmatrix lane constants (valid for wid<8)
    int rloc = lane & 15;
    uint32_t aRow = (uint32_t)(((wid & 7) * 16 + rloc) * 128);
    uint32_t aHi  = (uint32_t)(lane >> 4);
    uint32_t aRx  = (uint32_t)(rloc & 7);
    int nloc = (lane & 7) + ((lane >> 4) << 3);
    uint32_t bKh = (uint32_t)((lane >> 3) & 1);
    uint32_t bNx = (uint32_t)(lane & 7);
    uint32_t bRow = (uint32_t)(nloc * 128);

    // ffma lane geometry (valid for wid>=8): wg2 in 0..255 -> row r_ff, col-group cg
    int wg2 = tid - 256;
    int r_ff = wg2 >> 1;           // 0..127
    int cg   = wg2 & 1;            // 0/1 -> cols 48..55 / 56..63

    float4 v[4];
    int4 bh0, bl0;
    float4 btv;

    auto issue_loads = [&](int ci) {
#pragma unroll
        for (int q = 0; q < 4; q++) {
            int li = q * 512 + tid;
            int row = li >> 4, qk = li & 15;
            v[q] = __ldg((const float4*)(adj + (long)(rb + row) * NN + (long)ci * KC) + qk);
        }
        if (tid < 384) {
            bh0 = __ldg((const int4*)g_Bh + (size_t)ci * 512 + tid);
            bl0 = __ldg((const int4*)g_Bl + (size_t)ci * 512 + tid);
        }
        if (tid < 256) btv = __ldg((const float4*)g_BT2 + (size_t)ci * 256 + tid);
    };

    auto store_chunk = [&](char* buf) {
#pragma unroll
        for (int q = 0; q < 4; q++) {
            int li = q * 512 + tid;
            int row = li >> 4, qk = li & 15;
            unsigned off = row * 128 + qk * 8;
            unsigned sw = off ^ ((row & 7) << 4);
            uint32_t h01, h23, l01, l23;
            asm("cvt.rn.bf16x2.f32 %0, %1, %2;" : "=r"(h01) : "f"(v[q].y), "f"(v[q].x));
            asm("cvt.rn.bf16x2.f32 %0, %1, %2;" : "=r"(h23) : "f"(v[q].w), "f"(v[q].z));
            float lx = v[q].x - __uint_as_float(h01 << 16);
            float ly = v[q].y - __uint_as_float(h01 & 0xffff0000u);
            float lz = v[q].z - __uint_as_float(h23 << 16);
            float lw = v[q].w - __uint_as_float(h23 & 0xffff0000u);
            asm("cvt.rn.bf16x2.f32 %0, %1, %2;" : "=r"(l01) : "f"(ly), "f"(lx));
            asm("cvt.rn.bf16x2.f32 %0, %1, %2;" : "=r"(l23) : "f"(lw), "f"(lz));
            *(uint2*)(buf + AHo + sw) = make_uint2(h01, h23);
            *(uint2*)(buf + ALo + sw) = make_uint2(l01, l23);
            *(float4*)(buf + ADJFo + (row * ADJ_STR + qk * 4) * 4) = v[q];
        }
        if (tid < 384) {
            ((int4*)(buf + BHo))[tid] = bh0;
            ((int4*)(buf + BLo))[tid] = bl0;
        }
        if (tid < 256) ((float4*)(buf + BFo))[tid] = btv;
    };

    auto compute_tensor = [&](uint32_t bufaddr) {
        uint32_t AH_ = bufaddr + AHo, AL_ = bufaddr + ALo;
        uint32_t BH_ = bufaddr + BHo, BL_ = bufaddr + BLo;
#pragma unroll
        for (int ks = 0; ks < 4; ks++) {
            uint32_t au = ((((uint32_t)(ks * 2)) + aHi) ^ aRx) << 4;
            uint32_t ah[4], al[4];
            LDMATRIX_X4(ah[0], ah[1], ah[2], ah[3], AH_ + aRow + au);
            LDMATRIX_X4(al[0], al[1], al[2], al[3], AL_ + aRow + au);
            uint32_t bu = ((((uint32_t)(ks * 2)) + bKh) ^ bNx) << 4;
#pragma unroll
            for (int ntp = 0; ntp < 3; ntp++) {
                uint32_t bh[4], bl[4];
                LDMATRIX_X4(bh[0], bh[1], bh[2], bh[3], BH_ + bRow + bu + ntp * 2048);
                LDMATRIX_X4(bl[0], bl[1], bl[2], bl[3], BL_ + bRow + bu + ntp * 2048);
                MMA16816(acc[2 * ntp],     ah[0], ah[1], ah[2], ah[3], bh[0], bh[1]);
                MMA16816(acc[2 * ntp],     al[0], al[1], al[2], al[3], bh[0], bh[1]);
                MMA16816(acc[2 * ntp],     ah[0], ah[1], ah[2], ah[3], bl[0], bl[1]);
                MMA16816(acc[2 * ntp + 1], ah[0], ah[1], ah[2], ah[3], bh[2], bh[3]);
                MMA16816(acc[2 * ntp + 1], al[0], al[1], al[2], al[3], bh[2], bh[3]);
                MMA16816(acc[2 * ntp + 1], ah[0], ah[1], ah[2], ah[3], bl[2], bl[3]);
            }
        }
    };

    auto compute_ffma = [&](char* buf) {
        const float* adjf = (const float*)(buf + ADJFo) + r_ff * ADJ_STR;
        const float* bf   = (const float*)(buf + BFo) + cg * 8;
#pragma unroll 4
        for (int k = 0; k < 64; k++) {
            float a = adjf[k];
            float4 b0 = *(const float4*)(bf + k * 16);
            float4 b1 = *(const float4*)(bf + k * 16 + 4);
            facc[0] = fmaf(a, b0.x, facc[0]);
            facc[1] = fmaf(a, b0.y, facc[1]);
            facc[2] = fmaf(a, b0.z, facc[2]);
            facc[3] = fmaf(a, b0.w, facc[3]);
            facc[4] = fmaf(a, b1.x, facc[4]);
            facc[5] = fmaf(a, b1.y, facc[5]);
            facc[6] = fmaf(a, b1.z, facc[6]);
            facc[7] = fmaf(a, b1.w, facc[7]);
        }
    };

    issue_loads(c0);
    store_chunk(sm);
    __syncthreads();

    for (int it = 0; it < NCH_H; it++) {
        int s = it & 1;
        if (it + 1 < NCH_H) issue_loads(c0 + it + 1);
        if (wid < 8) compute_tensor(smb + s * BUFSZ);
        else         compute_ffma(sm + s * BUFSZ);
        if (it + 1 < NCH_H) store_chunk(sm + (s ^ 1) * BUFSZ);
        __syncthreads();
    }

    // epilogue
    float* hp = g_Hpart + (size_t)half * NN * NHID;
    if (wid < 8) {
        int r0 = rb + wid * 16 + (lane >> 2);
        int ncol = 2 * (lane & 3);
#pragma unroll
        for (int nt = 0; nt < 6; nt++) {
            *(float2*)(hp + (size_t)r0 * NHID + nt * 8 + ncol)       = make_float2(acc[nt][0], acc[nt][1]);
            *(float2*)(hp + (size_t)(r0 + 8) * NHID + nt * 8 + ncol) = make_float2(acc[nt][2], acc[nt][3]);
        }
    } else {
        int row_g = rb + r_ff;
        *(float4*)(hp + (size_t)row_g * NHID + 48 + cg * 8)     = make_float4(facc[0], facc[1], facc[2], facc[3]);
        *(float4*)(hp + (size_t)row_g * NHID + 48 + cg * 8 + 4) = make_float4(facc[4], facc[5], facc[6], facc[7]);
    }
}

// ===================== K2b: combine halves, +b1, relu, @W2 -> g_G =====================

__global__ __launch_bounds__(256) void k2b_combine(const float* __restrict__ b1,
                                                   const float* __restrict__ W2) {
    __shared__ float sb1[64];
    __shared__ float sW2[128];
    int tid = threadIdx.x;
    if (tid < 64)  sb1[tid] = b1[tid];
    if (tid >= 128 && tid < 256) sW2[tid - 128] = W2[tid - 128];
    __syncthreads();

    int row = blockIdx.x * 256 + tid;
    const float4* p0 = (const float4*)(g_Hpart) + (size_t)row * 16;
    const float4* p1 = (const float4*)(g_Hpart + (size_t)NN * NHID) + (size_t)row * 16;
    float g0 = 0.f, g1 = 0.f;
#pragma unroll
    for (int i = 0; i < 16; i++) {
        float4 a = __ldg(p0 + i);
        float4 b = __ldg(p1 + i);
        int n = i * 4;
        float h;
        h = fmaxf(a.x + b.x + sb1[n + 0], 0.f); g0 = fmaf(h, sW2[2*n + 0], g0); g1 = fmaf(h, sW2[2*n + 1], g1);
        h = fmaxf(a.y + b.y + sb1[n + 1], 0.f); g0 = fmaf(h, sW2[2*n + 2], g0); g1 = fmaf(h, sW2[2*n + 3], g1);
        h = fmaxf(a.z + b.z + sb1[n + 2], 0.f); g0 = fmaf(h, sW2[2*n + 4], g0); g1 = fmaf(h, sW2[2*n + 5], g1);
        h = fmaxf(a.w + b.w + sb1[n + 3], 0.f); g0 = fmaf(h, sW2[2*n + 6], g0); g1 = fmaf(h, sW2[2*n + 7], g1);
    }
    ((float2*)g_G)[row] = make_float2(g0, g1);
}

// ===================== K3: pass 2 — H2 = adj @ G, per-warp max (proven 174.5us version) =====================

__global__ __launch_bounds__(128) void k3_pass2(const float* __restrict__ adj) {
    int tid = threadIdx.x, wid = tid >> 5, lane = tid & 31;
    int grp = blockIdx.x * 4 + wid;               // 0..4095

    const float4* a0p = (const float4*)(adj + (size_t)grp * NN);
    const float4* a1p = (const float4*)(adj + (size_t)(grp + 4096) * NN);
    const float4* a2p = (const float4*)(adj + (size_t)(grp + 8192) * NN);
    const float4* a3p = (const float4*)(adj + (size_t)(grp + 12288) * NN);
    const float4* g4 = (const float4*)g_G;

    float s00 = 0.f, s01 = 0.f, s10 = 0.f, s11 = 0.f;
    float s20 = 0.f, s21 = 0.f, s30 = 0.f, s31 = 0.f;

    float4 A0 = __ldcs(a0p + lane);
    float4 A1 = __ldcs(a1p + lane);
    float4 A2 = __ldcs(a2p + lane);
    float4 A3 = __ldcs(a3p + lane);
    float4 G0 = __ldg(g4 + 2 * lane);
    float4 G1 = __ldg(g4 + 2 * lane + 1);

#define K3_FMA() do { \
        s00 = fmaf(A0.x, G0.x, s00); s01 = fmaf(A0.x, G0.y, s01); \
        s10 = fmaf(A1.x, G0.x, s10); s11 = fmaf(A1.x, G0.y, s11); \
        s20 = fmaf(A2.x, G0.x, s20); s21 = fmaf(A2.x, G0.y, s21); \
        s30 = fmaf(A3.x, G0.x, s30); s31 = fmaf(A3.x, G0.y, s31); \
        s00 = fmaf(A0.y, G0.z, s00); s01 = fmaf(A0.y, G0.w, s01); \
        s10 = fmaf(A1.y, G0.z, s10); s11 = fmaf(A1.y, G0.w, s11); \
        s20 = fmaf(A2.y, G0.z, s20); s21 = fmaf(A2.y, G0.w, s21); \
        s30 = fmaf(A3.y, G0.z, s30); s31 = fmaf(A3.y, G0.w, s31); \
        s00 = fmaf(A0.z, G1.x, s00); s01 = fmaf(A0.z, G1.y, s01); \
        s10 = fmaf(A1.z, G1.x, s10); s11 = fmaf(A1.z, G1.y, s11); \
        s20 = fmaf(A2.z, G1.x, s20); s21 = fmaf(A2.z, G1.y, s21); \
        s30 = fmaf(A3.z, G1.x, s30); s31 = fmaf(A3.z, G1.y, s31); \
        s00 = fmaf(A0.w, G1.z, s00); s01 = fmaf(A0.w, G1.w, s01); \
        s10 = fmaf(A1.w, G1.z, s10); s11 = fmaf(A1.w, G1.w, s11); \
        s20 = fmaf(A2.w, G1.z, s20); s21 = fmaf(A2.w, G1.w, s21); \
        s30 = fmaf(A3.w, G1.z, s30); s31 = fmaf(A3.w, G1.w, s31); \
    } while (0)

    for (int it = 1; it < 128; it++) {
        int j4 = it * 32 + lane;
        float4 nA0 = __ldcs(a0p + j4);
        float4 nA1 = __ldcs(a1p + j4);
        float4 nA2 = __ldcs(a2p + j4);
        float4 nA3 = __ldcs(a3p + j4);
        float4 nG0 = __ldg(g4 + 2 * j4);
        float4 nG1 = __ldg(g4 + 2 * j4 + 1);
        K3_FMA();
        A0 = nA0; A1 = nA1; A2 = nA2; A3 = nA3; G0 = nG0; G1 = nG1;
    }
    K3_FMA();
#undef K3_FMA

#pragma unroll
    for (int o = 16; o; o >>= 1) {
        s00 += __shfl_xor_sync(0xFFFFFFFFu, s00, o);
        s01 += __shfl_xor_sync(0xFFFFFFFFu, s01, o);
        s10 += __shfl_xor_sync(0xFFFFFFFFu, s10, o);
        s11 += __shfl_xor_sync(0xFFFFFFFFu, s11, o);
        s20 += __shfl_xor_sync(0xFFFFFFFFu, s20, o);
        s21 += __shfl_xor_sync(0xFFFFFFFFu, s21, o);
        s30 += __shfl_xor_sync(0xFFFFFFFFu, s30, o);
        s31 += __shfl_xor_sync(0xFFFFFFFFu, s31, o);
    }
    if (lane == 0) {
        float m0 = fmaxf(fmaxf(s00, s10), fmaxf(s20, s30));
        float m1 = fmaxf(fmaxf(s01, s11), fmaxf(s21, s31));
        g_pmax[grp * 2]     = m0;
        g_pmax[grp * 2 + 1] = m1;
    }
}

// ===================== K4: final max reduce + Linear(2 -> 1) =====================

__global__ void k4_final(const float* __restrict__ W3, const float* __restrict__ b2,
                         const float* __restrict__ b3, float* __restrict__ out) {
    __shared__ float r[16];
    int tid = threadIdx.x;   // 256
    float m0 = -3.402823466e38f, m1 = -3.402823466e38f;
#pragma unroll
    for (int i = 0; i < (K3_GRID * 4) / 256; i++) {
        float2 p = ((const float2*)g_pmax)[i * 256 + tid];
        m0 = fmaxf(m0, p.x);
        m1 = fmaxf(m1, p.y);
    }
#pragma unroll
    for (int o = 16; o; o >>= 1) {
        m0 = fmaxf(m0, __shfl_xor_sync(0xFFFFFFFFu, m0, o));
        m1 = fmaxf(m1, __shfl_xor_sync(0xFFFFFFFFu, m1, o));
    }
    if ((tid & 31) == 0) { r[(tid >> 5) * 2] = m0; r[(tid >> 5) * 2 + 1] = m1; }
    __syncthreads();
    if (tid == 0) {
        float M0 = r[0], M1 = r[1];
#pragma unroll
        for (int w = 1; w < 8; w++) { M0 = fmaxf(M0, r[2 * w]); M1 = fmaxf(M1, r[2 * w + 1]); }
        M0 += b2[0];
        M1 += b2[1];
        out[0] = fmaf(M0, W3[0], fmaf(M1, W3[1], b3[0]));
    }
}

// ===================== Launch =====================

extern "C" void kernel_launch(void* const* d_in, const int* in_sizes, int n_in,
                              void* d_out, int out_size) {
    const float* x   = (const float*)d_in[0];
    const float* adj = (const float*)d_in[1];
    const float* W1  = (const float*)d_in[2];
    const float* b1  = (const float*)d_in[3];
    const float* W2  = (const float*)d_in[4];
    const float* b2  = (const float*)d_in[5];
    const float* W3  = (const float*)d_in[6];
    const float* b3  = (const float*)d_in[7];
    float* out = (float*)d_out;

    cudaFuncSetAttribute(k1_xw1,   cudaFuncAttributeMaxDynamicSharedMemorySize, 81920);
    cudaFuncSetAttribute(k2_pass1, cudaFuncAttributeMaxDynamicSharedMemorySize, SMEM_K2);

    k1_xw1<<<256, 256, 81920>>>(x, W1);
    k2_pass1<<<NMT * KSPLIT, 512, SMEM_K2>>>(adj);
    k2b_combine<<<64, 256>>>(b1, W2);
    k3_pass2<<<K3_GRID, 128>>>(adj);
    k4_final<<<1, 256>>>(W3, b2, b3, out);
}

// round 13
// speedup vs baseline: 3.2931x; 2.5014x over previous
#include <cuda_runtime.h>
#include <cuda_bf16.h>
#include <cstdint>

// ===================== helpers =====================

__device__ __forceinline__ uint32_t smem_u32(const void* p) {
    uint32_t a;
    asm("{ .reg .u64 t; cvta.to.shared.u64 t, %1; cvt.u32.u64 %0, t; }" : "=r"(a) : "l"(p));
    return a;
}

#define LDMATRIX_X4(r0, r1, r2, r3, addr) \
    asm volatile("ldmatrix.sync.aligned.m8n8.x4.shared.b16 {%0,%1,%2,%3}, [%4];" \
        : "=r"(r0), "=r"(r1), "=r"(r2), "=r"(r3) : "r"(addr))

#define MMA16816(c, a0, a1, a2, a3, b0, b1) \
    asm volatile("mma.sync.aligned.m16n8k16.row.col.f32.bf16.bf16.f32 " \
        "{%0,%1,%2,%3}, {%4,%5,%6,%7}, {%8,%9}, {%0,%1,%2,%3};" \
        : "+f"((c)[0]), "+f"((c)[1]), "+f"((c)[2]), "+f"((c)[3]) \
        : "r"(a0), "r"(a1), "r"(a2), "r"(a3), "r"(b0), "r"(b1))

// ===================== Problem constants =====================

#define NN      16384
#define NFEAT   256
#define NHID    64
#define KC      64             // K chunk per pipeline step
#define NCHUNK  (NN / KC)      // 256
#define MTILE   128
#define NMT     (NN / MTILE)   // 128 M-tiles
#define KSPLIT  16             // K slices (units per M-tile)
#define CPU_    16             // chunks per unit (256/16)
#define NUNITS  (NMT * KSPLIT) // 2048
#define NWORK   296            // persistent workers (148 SMs x 2 CTAs)
#define K3_GRID 1024           // x 4 warps = 4096 row-groups of 4 rows

// Scratch (static device globals — allocation-free)
__device__ __align__(16) unsigned char g_Bh[NCHUNK * 8192];    // pre-swizzled bf16 hi tiles [chunk][64n x 64k]
__device__ __align__(16) unsigned char g_Bl[NCHUNK * 8192];    // bf16 lo tiles
__device__ __align__(16) float g_Hpart[KSPLIT * NN * NHID];    // partial pre-activation sums (64MB)
__device__ __align__(16) float g_G[NN * 2];                    // h1 @ W2 (before +b2)
__device__ __align__(16) float g_pmax[K3_GRID * 4 * 2];        // per-warp column maxes

// ===================== K1: B = x @ W1, split to bf16 hi/lo, pre-swizzled =====================

__global__ __launch_bounds__(256) void k1_xw1(const float* __restrict__ x, const float* __restrict__ W1) {
    extern __shared__ char sm1[];
    float* W1s = (float*)sm1;                        // 65536 B
    unsigned char* bh = (unsigned char*)sm1 + 65536; // 8192 B
    unsigned char* bl = bh + 8192;

    int tid = threadIdx.x, wid = tid >> 5, lid = tid & 31;

    const float4* w4 = (const float4*)W1;
    float4* w4s = (float4*)W1s;
#pragma unroll
    for (int i = 0; i < 16; i++) w4s[tid + i * 256] = w4[tid + i * 256];
    __syncthreads();

    int b = blockIdx.x;   // chunk index; covers global k rows [64b, 64b+64)
    for (int i = 0; i < 8; i++) {
        int kl = wid * 8 + i;                 // local k row 0..63
        long k = (long)b * 64 + kl;
        const float* xr = x + k * 256;
        float a0 = 0.f, a1 = 0.f;             // n = 2*lid, 2*lid+1
#pragma unroll 8
        for (int j = 0; j < 256; j++) {
            float xv = __ldg(xr + j);
            float2 wv = *(const float2*)(W1s + j * 64 + 2 * lid);
            a0 = fmaf(xv, wv.x, a0);
            a1 = fmaf(xv, wv.y, a1);
        }
#pragma unroll
        for (int t = 0; t < 2; t++) {
            float a = t ? a1 : a0;
            int n = 2 * lid + t;
            unsigned off = n * 128 + kl * 2;
            unsigned sw = off ^ ((off >> 3) & 0x70);
            __nv_bfloat16 h = __float2bfloat16(a);
            __nv_bfloat16 l = __float2bfloat16(a - __bfloat162float(h));
            *(__nv_bfloat16*)(bh + sw) = h;
            *(__nv_bfloat16*)(bl + sw) = l;
        }
    }
    __syncthreads();

    int4* gh = (int4*)g_Bh + (size_t)b * 512;
    int4* gl = (int4*)g_Bl + (size_t)b * 512;
    const int4* sh = (const int4*)bh;
    const int4* sl = (const int4*)bl;
#pragma unroll
    for (int i = 0; i < 2; i++) {
        gh[tid + i * 256] = sh[tid + i * 256];
        gl[tid + i * 256] = sl[tid + i * 256];
    }
}

// ===================== K2: pass 1 — persistent workers over 2048 (M-tile x K-slice) units =====================
// grid 296 (one wave at 2 CTAs/SM), block 256. Worker w handles units w, w+296, ... (6-7 units).
// Unit = 16 chunks; fp32->bf16 hi/lo Markidis 3-term; pipeline continues across unit boundaries,
// only the register accumulators flush to g_Hpart[slice] at unit end.

__global__ __launch_bounds__(256, 2) void k2_pass1(const float* __restrict__ adj) {
    extern __shared__ char sm2raw[];
    uint32_t raw = smem_u32(sm2raw);
    uint32_t pad = (1024u - (raw & 1023u)) & 1023u;
    char* sm = sm2raw + pad;
    uint32_t smb = raw + pad;

    const int BUFSZ = 49152;

    int tid = threadIdx.x, wid = tid >> 5, lane = tid & 31;
    int wkr = blockIdx.x;

    int nu = (NUNITS - wkr + NWORK - 1) / NWORK;   // 6 or 7
    int total = nu * CPU_;

    float acc[8][4];
#pragma unroll
    for (int i = 0; i < 8; i++)
#pragma unroll
        for (int j = 0; j < 4; j++) acc[i][j] = 0.f;

    int rloc = lane & 15;
    uint32_t aRow = (uint32_t)((wid * 16 + rloc) * 128);
    uint32_t aHi  = (uint32_t)(lane >> 4);
    uint32_t aRx  = (uint32_t)(rloc & 7);
    int nloc = (lane & 7) + ((lane >> 4) << 3);
    uint32_t bKh = (uint32_t)((lane >> 3) & 1);
    uint32_t bNx = (uint32_t)(lane & 7);
    uint32_t bRow = (uint32_t)(nloc * 128);

    float4 v[8];
    int4 bh0, bh1, bl0, bl1;

    // unit/chunk arithmetic (no arrays -> no local memory)
    auto unit_of = [&](int j) { return wkr + (j >> 4) * NWORK; };
    auto rb_of   = [&](int j) { return (unit_of(j) >> 4) * MTILE; };
    auto ci_of   = [&](int j) { int u = unit_of(j); return (u & 15) * CPU_ + (j & 15); };

    auto issue_loads = [&](int rb, int ci) {
#pragma unroll
        for (int q = 0; q < 8; q++) {
            int li = q * 256 + tid;
            int row = li >> 4, qk = li & 15;
            v[q] = __ldg((const float4*)(adj + (long)(rb + row) * NN + (long)ci * KC) + qk);
        }
        const int4* gbh = (const int4*)g_Bh + (size_t)ci * 512;
        const int4* gbl = (const int4*)g_Bl + (size_t)ci * 512;
        bh0 = __ldg(gbh + tid); bh1 = __ldg(gbh + tid + 256);
        bl0 = __ldg(gbl + tid); bl1 = __ldg(gbl + tid + 256);
    };

    auto store_chunk = [&](char* buf) {
#pragma unroll
        for (int q = 0; q < 8; q++) {
            int li = q * 256 + tid;
            int row = li >> 4, qk = li & 15;
            unsigned off = row * 128 + qk * 8;
            unsigned sw = off ^ ((row & 7) << 4);
            uint32_t h01, h23, l01, l23;
            asm("cvt.rn.bf16x2.f32 %0, %1, %2;" : "=r"(h01) : "f"(v[q].y), "f"(v[q].x));
            asm("cvt.rn.bf16x2.f32 %0, %1, %2;" : "=r"(h23) : "f"(v[q].w), "f"(v[q].z));
            float lx = v[q].x - __uint_as_float(h01 << 16);
            float ly = v[q].y - __uint_as_float(h01 & 0xffff0000u);
            float lz = v[q].z - __uint_as_float(h23 << 16);
            float lw = v[q].w - __uint_as_float(h23 & 0xffff0000u);
            asm("cvt.rn.bf16x2.f32 %0, %1, %2;" : "=r"(l01) : "f"(ly), "f"(lx));
            asm("cvt.rn.bf16x2.f32 %0, %1, %2;" : "=r"(l23) : "f"(lw), "f"(lz));
            *(uint2*)(buf + 0     + sw) = make_uint2(h01, h23);
            *(uint2*)(buf + 16384 + sw) = make_uint2(l01, l23);
        }
        ((int4*)(buf + 32768))[tid] = bh0; ((int4*)(buf + 32768))[tid + 256] = bh1;
        ((int4*)(buf + 40960))[tid] = bl0; ((int4*)(buf + 40960))[tid + 256] = bl1;
    };

    auto compute = [&](uint32_t bufaddr) {
        uint32_t AH_ = bufaddr, AL_ = bufaddr + 16384;
        uint32_t BH_ = bufaddr + 32768, BL_ = bufaddr + 40960;
#pragma unroll
        for (int ks = 0; ks < 4; ks++) {
            uint32_t au = ((((uint32_t)(ks * 2)) + aHi) ^ aRx) << 4;
            uint32_t ah[4], al[4];
            LDMATRIX_X4(ah[0], ah[1], ah[2], ah[3], AH_ + aRow + au);
            LDMATRIX_X4(al[0], al[1], al[2], al[3], AL_ + aRow + au);
            uint32_t bu = ((((uint32_t)(ks * 2)) + bKh) ^ bNx) << 4;
#pragma unroll
            for (int ntp = 0; ntp < 4; ntp++) {
                uint32_t bh[4], bl[4];
                LDMATRIX_X4(bh[0], bh[1], bh[2], bh[3], BH_ + bRow + bu + ntp * 2048);
                LDMATRIX_X4(bl[0], bl[1], bl[2], bl[3], BL_ + bRow + bu + ntp * 2048);
                MMA16816(acc[2 * ntp],     ah[0], ah[1], ah[2], ah[3], bh[0], bh[1]);
                MMA16816(acc[2 * ntp],     al[0], al[1], al[2], al[3], bh[0], bh[1]);
                MMA16816(acc[2 * ntp],     ah[0], ah[1], ah[2], ah[3], bl[0], bl[1]);
                MMA16816(acc[2 * ntp + 1], ah[0], ah[1], ah[2], ah[3], bh[2], bh[3]);
                MMA16816(acc[2 * ntp + 1], al[0], al[1], al[2], al[3], bh[2], bh[3]);
                MMA16816(acc[2 * ntp + 1], ah[0], ah[1], ah[2], ah[3], bl[2], bl[3]);
            }
        }
    };

    issue_loads(rb_of(0), ci_of(0));
    store_chunk(sm);
    __syncthreads();

    for (int j = 0; j < total; j++) {
        int s = j & 1;
        if (j + 1 < total) issue_loads(rb_of(j + 1), ci_of(j + 1));
        compute(smb + s * BUFSZ);
        if ((j & 15) == 15) {
            // flush accumulators for completed unit
            int u = unit_of(j);
            float* hp = g_Hpart + (size_t)(u & 15) * NN * NHID;
            int r0 = (u >> 4) * MTILE + wid * 16 + (lane >> 2);
            int ncol = 2 * (lane & 3);
#pragma unroll
            for (int nt = 0; nt < 8; nt++) {
                *(float2*)(hp + (size_t)r0 * NHID + nt * 8 + ncol)       = make_float2(acc[nt][0], acc[nt][1]);
                *(float2*)(hp + (size_t)(r0 + 8) * NHID + nt * 8 + ncol) = make_float2(acc[nt][2], acc[nt][3]);
                acc[nt][0] = 0.f; acc[nt][1] = 0.f; acc[nt][2] = 0.f; acc[nt][3] = 0.f;
            }
        }
        if (j + 1 < total) store_chunk(sm + (s ^ 1) * BUFSZ);
        __syncthreads();
    }
}

// ===================== K2b: combine 16 slices, +b1, relu, @W2 -> g_G =====================
// grid 1024, block 256: half-warp per row (coalesced 256B row loads per half-warp).

__global__ __launch_bounds__(256) void k2b_combine(const float* __restrict__ b1,
                                                   const float* __restrict__ W2) {
    __shared__ float sb1[64];
    __shared__ float sW2[128];
    int tid = threadIdx.x, wid = tid >> 5, lane = tid & 31;
    if (tid < 64)  sb1[tid] = b1[tid];
    if (tid >= 128 && tid < 256) sW2[tid - 128] = W2[tid - 128];
    __syncthreads();

    int row = blockIdx.x * 16 + wid * 2 + (lane >> 4);   // 0..16383
    int cl = lane & 15;                                   // col group (4 cols)

    float4 s = make_float4(0.f, 0.f, 0.f, 0.f);
#pragma unroll
    for (int sl = 0; sl < KSPLIT; sl++) {
        float4 a = __ldg((const float4*)(g_Hpart + (size_t)sl * NN * NHID + (size_t)row * NHID) + cl);
        s.x += a.x; s.y += a.y; s.z += a.z; s.w += a.w;
    }
    int n = cl * 4;
    float g0 = 0.f, g1 = 0.f, h;
    h = fmaxf(s.x + sb1[n + 0], 0.f); g0 = fmaf(h, sW2[2*n + 0], g0); g1 = fmaf(h, sW2[2*n + 1], g1);
    h = fmaxf(s.y + sb1[n + 1], 0.f); g0 = fmaf(h, sW2[2*n + 2], g0); g1 = fmaf(h, sW2[2*n + 3], g1);
    h = fmaxf(s.z + sb1[n + 2], 0.f); g0 = fmaf(h, sW2[2*n + 4], g0); g1 = fmaf(h, sW2[2*n + 5], g1);
    h = fmaxf(s.w + sb1[n + 3], 0.f); g0 = fmaf(h, sW2[2*n + 6], g0); g1 = fmaf(h, sW2[2*n + 7], g1);
#pragma unroll
    for (int o = 1; o <= 8; o <<= 1) {
        g0 += __shfl_xor_sync(0xFFFFFFFFu, g0, o);
        g1 += __shfl_xor_sync(0xFFFFFFFFu, g1, o);
    }
    if (cl == 0) ((float2*)g_G)[row] = make_float2(g0, g1);
}

// ===================== K3: pass 2 — H2 = adj @ G, per-warp max (proven 168.9us version) =====================

__global__ __launch_bounds__(128) void k3_pass2(const float* __restrict__ adj) {
    int tid = threadIdx.x, wid = tid >> 5, lane = tid & 31;
    int grp = blockIdx.x * 4 + wid;               // 0..4095

    const float4* a0p = (const float4*)(adj + (size_t)grp * NN);
    const float4* a1p = (const float4*)(adj + (size_t)(grp + 4096) * NN);
    const float4* a2p = (const float4*)(adj + (size_t)(grp + 8192) * NN);
    const float4* a3p = (const float4*)(adj + (size_t)(grp + 12288) * NN);
    const float4* g4 = (const float4*)g_G;

    float s00 = 0.f, s01 = 0.f, s10 = 0.f, s11 = 0.f;
    float s20 = 0.f, s21 = 0.f, s30 = 0.f, s31 = 0.f;

    float4 A0 = __ldcs(a0p + lane);
    float4 A1 = __ldcs(a1p + lane);
    float4 A2 = __ldcs(a2p + lane);
    float4 A3 = __ldcs(a3p + lane);
    float4 G0 = __ldg(g4 + 2 * lane);
    float4 G1 = __ldg(g4 + 2 * lane + 1);

#define K3_FMA() do { \
        s00 = fmaf(A0.x, G0.x, s00); s01 = fmaf(A0.x, G0.y, s01); \
        s10 = fmaf(A1.x, G0.x, s10); s11 = fmaf(A1.x, G0.y, s11); \
        s20 = fmaf(A2.x, G0.x, s20); s21 = fmaf(A2.x, G0.y, s21); \
        s30 = fmaf(A3.x, G0.x, s30); s31 = fmaf(A3.x, G0.y, s31); \
        s00 = fmaf(A0.y, G0.z, s00); s01 = fmaf(A0.y, G0.w, s01); \
        s10 = fmaf(A1.y, G0.z, s10); s11 = fmaf(A1.y, G0.w, s11); \
        s20 = fmaf(A2.y, G0.z, s20); s21 = fmaf(A2.y, G0.w, s21); \
        s30 = fmaf(A3.y, G0.z, s30); s31 = fmaf(A3.y, G0.w, s31); \
        s00 = fmaf(A0.z, G1.x, s00); s01 = fmaf(A0.z, G1.y, s01); \
        s10 = fmaf(A1.z, G1.x, s10); s11 = fmaf(A1.z, G1.y, s11); \
        s20 = fmaf(A2.z, G1.x, s20); s21 = fmaf(A2.z, G1.y, s21); \
        s30 = fmaf(A3.z, G1.x, s30); s31 = fmaf(A3.z, G1.y, s31); \
        s00 = fmaf(A0.w, G1.z, s00); s01 = fmaf(A0.w, G1.w, s01); \
        s10 = fmaf(A1.w, G1.z, s10); s11 = fmaf(A1.w, G1.w, s11); \
        s20 = fmaf(A2.w, G1.z, s20); s21 = fmaf(A2.w, G1.w, s21); \
        s30 = fmaf(A3.w, G1.z, s30); s31 = fmaf(A3.w, G1.w, s31); \
    } while (0)

    for (int it = 1; it < 128; it++) {
        int j4 = it * 32 + lane;
        float4 nA0 = __ldcs(a0p + j4);
        float4 nA1 = __ldcs(a1p + j4);
        float4 nA2 = __ldcs(a2p + j4);
        float4 nA3 = __ldcs(a3p + j4);
        float4 nG0 = __ldg(g4 + 2 * j4);
        float4 nG1 = __ldg(g4 + 2 * j4 + 1);
        K3_FMA();
        A0 = nA0; A1 = nA1; A2 = nA2; A3 = nA3; G0 = nG0; G1 = nG1;
    }
    K3_FMA();
#undef K3_FMA

#pragma unroll
    for (int o = 16; o; o >>= 1) {
        s00 += __shfl_xor_sync(0xFFFFFFFFu, s00, o);
        s01 += __shfl_xor_sync(0xFFFFFFFFu, s01, o);
        s10 += __shfl_xor_sync(0xFFFFFFFFu, s10, o);
        s11 += __shfl_xor_sync(0xFFFFFFFFu, s11, o);
        s20 += __shfl_xor_sync(0xFFFFFFFFu, s20, o);
        s21 += __shfl_xor_sync(0xFFFFFFFFu, s21, o);
        s30 += __shfl_xor_sync(0xFFFFFFFFu, s30, o);
        s31 += __shfl_xor_sync(0xFFFFFFFFu, s31, o);
    }
    if (lane == 0) {
        float m0 = fmaxf(fmaxf(s00, s10), fmaxf(s20, s30));
        float m1 = fmaxf(fmaxf(s01, s11), fmaxf(s21, s31));
        g_pmax[grp * 2]     = m0;
        g_pmax[grp * 2 + 1] = m1;
    }
}

// ===================== K4: final max reduce + Linear(2 -> 1) =====================

__global__ void k4_final(const float* __restrict__ W3, const float* __restrict__ b2,
                         const float* __restrict__ b3, float* __restrict__ out) {
    __shared__ float r[16];
    int tid = threadIdx.x;   // 256
    float m0 = -3.402823466e38f, m1 = -3.402823466e38f;
#pragma unroll
    for (int i = 0; i < (K3_GRID * 4) / 256; i++) {
        float2 p = ((const float2*)g_pmax)[i * 256 + tid];
        m0 = fmaxf(m0, p.x);
        m1 = fmaxf(m1, p.y);
    }
#pragma unroll
    for (int o = 16; o; o >>= 1) {
        m0 = fmaxf(m0, __shfl_xor_sync(0xFFFFFFFFu, m0, o));
        m1 = fmaxf(m1, __shfl_xor_sync(0xFFFFFFFFu, m1, o));
    }
    if ((tid & 31) == 0) { r[(tid >> 5) * 2] = m0; r[(tid >> 5) * 2 + 1] = m1; }
    __syncthreads();
    if (tid == 0) {
        float M0 = r[0], M1 = r[1];
#pragma unroll
        for (int w = 1; w < 8; w++) { M0 = fmaxf(M0, r[2 * w]); M1 = fmaxf(M1, r[2 * w + 1]); }
        M0 += b2[0];
        M1 += b2[1];
        out[0] = fmaf(M0, W3[0], fmaf(M1, W3[1], b3[0]));
    }
}

// ===================== Launch =====================

extern "C" void kernel_launch(void* const* d_in, const int* in_sizes, int n_in,
                              void* d_out, int out_size) {
    const float* x   = (const float*)d_in[0];
    const float* adj = (const float*)d_in[1];
    const float* W1  = (const float*)d_in[2];
    const float* b1  = (const float*)d_in[3];
    const float* W2  = (const float*)d_in[4];
    const float* b2  = (const float*)d_in[5];
    const float* W3  = (const float*)d_in[6];
    const float* b3  = (const float*)d_in[7];
    float* out = (float*)d_out;

    cudaFuncSetAttribute(k1_xw1,   cudaFuncAttributeMaxDynamicSharedMemorySize, 81920);
    cudaFuncSetAttribute(k2_pass1, cudaFuncAttributeMaxDynamicSharedMemorySize, 99328);

    k1_xw1<<<256, 256, 81920>>>(x, W1);
    k2_pass1<<<NWORK, 256, 99328>>>(adj);
    k2b_combine<<<1024, 256>>>(b1, W2);
    k3_pass2<<<K3_GRID, 128>>>(adj);
    k4_final<<<1, 256>>>(W3, b2, b3, out);
}